// round 1
// baseline (speedup 1.0000x reference)
#include <cuda_runtime.h>
#include <cstdint>

// Problem constants (fixed shapes from the reference)
#define TT 16
#define HH 1280
#define WW 1280
#define NB 64
#define HW (HH * WW)          // 1,638,400
#define HW4 (HW / 4)          // 409,600 float4 per frame
#define W4 (WW / 4)           // 320

// Scratch (no cudaMalloc allowed) — device globals.
__device__ unsigned long long g_ymask[HH];
__device__ unsigned long long g_xmask[WW];
__device__ double g_acc;

// ---------------------------------------------------------------------------
// Kernel 1: build per-row / per-column 64-bit box coverage masks.
// Also zero the accumulator (runs first in the graph every replay).
// ---------------------------------------------------------------------------
__global__ void masks_kernel(const int* __restrict__ boxes) {
    int i = blockIdx.x * blockDim.x + threadIdx.x;
    if (i == 0) g_acc = 0.0;
    if (i >= HH) return;  // HH == WW
    unsigned long long ym = 0ull, xm = 0ull;
#pragma unroll
    for (int n = 0; n < NB; n++) {
        int x1 = boxes[4 * n + 0];
        int y1 = boxes[4 * n + 1];
        int x2 = boxes[4 * n + 2];
        int y2 = boxes[4 * n + 3];
        if (y1 <= i && i < y2) ym |= (1ull << n);
        if (x1 <= i && i < x2) xm |= (1ull << n);
    }
    g_ymask[i] = ym;
    g_xmask[i] = xm;
}

// ---------------------------------------------------------------------------
// Kernel 2: streaming weighted reduction.
// Thread -> one float4 (4 consecutive x) of the (H,W) plane; loop over T=16
// frames fully unrolled for MLP. Weight = popc(ymask & xmask), t-invariant,
// applied once after the t-sum.
// ---------------------------------------------------------------------------
__global__ void __launch_bounds__(256) reduce_kernel(const float* __restrict__ data) {
    int gid = blockIdx.x * blockDim.x + threadIdx.x;  // 0 .. HW4-1
    int y = gid / W4;
    int xq = gid - y * W4;
    int x0 = xq * 4;

    unsigned long long ym = g_ymask[y];
    float w0 = (float)__popcll(ym & g_xmask[x0 + 0]);
    float w1 = (float)__popcll(ym & g_xmask[x0 + 1]);
    float w2 = (float)__popcll(ym & g_xmask[x0 + 2]);
    float w3 = (float)__popcll(ym & g_xmask[x0 + 3]);

    const float4* p = reinterpret_cast<const float4*>(data);
    float a0 = 0.f, a1 = 0.f, a2 = 0.f, a3 = 0.f;
#pragma unroll
    for (int t = 0; t < TT; t++) {
        float4 v = __ldg(&p[(size_t)t * HW4 + gid]);
        a0 += v.x; a1 += v.y; a2 += v.z; a3 += v.w;
    }
    float s = w0 * a0 + w1 * a1 + w2 * a2 + w3 * a3;

    // warp reduce
#pragma unroll
    for (int off = 16; off > 0; off >>= 1)
        s += __shfl_down_sync(0xFFFFFFFFu, s, off);

    // block reduce via shared
    __shared__ float warp_sums[8];
    int lane = threadIdx.x & 31;
    int wid = threadIdx.x >> 5;
    if (lane == 0) warp_sums[wid] = s;
    __syncthreads();
    if (wid == 0) {
        float b = (lane < 8) ? warp_sums[lane] : 0.f;
#pragma unroll
        for (int off = 4; off > 0; off >>= 1)
            b += __shfl_down_sync(0xFFFFFFFFu, b, off);
        if (lane == 0) atomicAdd(&g_acc, (double)b);
    }
}

// ---------------------------------------------------------------------------
// Kernel 3: write the scalar output.
// ---------------------------------------------------------------------------
__global__ void epilogue_kernel(float* __restrict__ out) {
    out[0] = (float)g_acc;
}

extern "C" void kernel_launch(void* const* d_in, const int* in_sizes, int n_in,
                              void* d_out, int out_size) {
    const float* data = (const float*)d_in[0];   // (16,1280,1280) fp32
    const int* boxes = (const int*)d_in[1];      // (64,4) int32 [x1,y1,x2,y2]
    float* out = (float*)d_out;

    masks_kernel<<<(HH + 255) / 256, 256>>>(boxes);
    reduce_kernel<<<HW4 / 256, 256>>>(data);     // 1600 blocks
    epilogue_kernel<<<1, 1>>>(out);
}